// round 14
// baseline (speedup 1.0000x reference)
#include <cuda_runtime.h>
#include <cuda_bf16.h>
#include <cuda_fp16.h>
#include <math.h>
#include <stdint.h>

#define BB 4
#define SS 4096
#define DD 128
#define HH 256
#define NTOK (BB*SS)
#define NT (SS/64)

#define ASCALE 1073741824.0f          // 2^30 attn pre-scale for fp16 PV
#define INV_ASCALE (1.0f/1073741824.0f)

// Operands (device globals: allocation-free rule)
__device__ __align__(16) __half g_qf[NTOK*DD];   // [tok][d] fp16
__device__ __align__(16) __half g_kf[NTOK*DD];   // [tok][d] fp16
__device__ __align__(16) __half g_vf[NTOK*HH];   // [b][h][s] fp16
__device__ float g_gate[NTOK*HH];                 // [tok][h] fp32

// Split-bf16 transposed weights (k_pre GEMMs keep full precision)
__device__ __align__(16) __nv_bfloat16 g_WqkT_h[DD*DD]; // [n][k]
__device__ __align__(16) __nv_bfloat16 g_WqkT_l[DD*DD];
__device__ __align__(16) __nv_bfloat16 g_WgT_h[HH*DD];  // [n][k]
__device__ __align__(16) __nv_bfloat16 g_WgT_l[HH*DD];

__device__ __forceinline__ float silu_f(float x) {
    return x / (1.0f + expf(-x));
}

__device__ __forceinline__ void bsplit(float x, unsigned short& hi, unsigned short& lo) {
    __nv_bfloat16 h = __float2bfloat16(x);
    __nv_bfloat16 l = __float2bfloat16(x - __bfloat162float(h));
    hi = __bfloat16_as_ushort(h);
    lo = __bfloat16_as_ushort(l);
}

#define LDSM4(r0, r1, r2, r3, a)                                              \
    asm volatile("ldmatrix.sync.aligned.m8n8.x4.shared.b16 {%0,%1,%2,%3},[%4];" \
                 : "=r"(r0), "=r"(r1), "=r"(r2), "=r"(r3) : "r"(a));

#define MMABF16(d, a0, a1, a2, a3, b0, b1)                                    \
    asm volatile("mma.sync.aligned.m16n8k16.row.col.f32.bf16.bf16.f32 "       \
                 "{%0,%1,%2,%3},{%4,%5,%6,%7},{%8,%9},{%0,%1,%2,%3};"         \
                 : "+f"(d[0]), "+f"(d[1]), "+f"(d[2]), "+f"(d[3])             \
                 : "r"(a0), "r"(a1), "r"(a2), "r"(a3), "r"(b0), "r"(b1));

#define MMAF16(d, a0, a1, a2, a3, b0, b1)                                     \
    asm volatile("mma.sync.aligned.m16n8k16.row.col.f32.f16.f16.f32 "         \
                 "{%0,%1,%2,%3},{%4,%5,%6,%7},{%8,%9},{%0,%1,%2,%3};"         \
                 : "+f"(d[0]), "+f"(d[1]), "+f"(d[2]), "+f"(d[3])             \
                 : "r"(a0), "r"(a1), "r"(a2), "r"(a3), "r"(b0), "r"(b1));

#define CP16(dst, src) \
    asm volatile("cp.async.cg.shared.global [%0], [%1], 16;" \
                 :: "r"(dst), "l"(src) : "memory")
#define CP_COMMIT() asm volatile("cp.async.commit_group;" ::: "memory")
#define CP_WAIT(n)  asm volatile("cp.async.wait_group %0;" :: "n"(n) : "memory")

// ---------------------------------------------------------------------------
// Kernel 0: weight transpose + split-bf16 conversion (tiny).
// ---------------------------------------------------------------------------
__global__ void __launch_bounds__(256) k_wconv(
    const float* __restrict__ Wqk, const float* __restrict__ Wg)
{
    const int i = blockIdx.x * 256 + threadIdx.x;
    unsigned short hi, lo;
    if (i < DD * DD) {
        const int n = i >> 7, k = i & 127;
        bsplit(Wqk[k * DD + n], hi, lo);
        g_WqkT_h[i] = __ushort_as_bfloat16(hi);
        g_WqkT_l[i] = __ushort_as_bfloat16(lo);
    }
    if (i < HH * DD) {
        const int n = i >> 7, k = i & 127;
        bsplit(Wg[k * HH + n], hi, lo);
        g_WgT_h[i] = __ushort_as_bfloat16(hi);
        g_WgT_l[i] = __ushort_as_bfloat16(lo);
    }
}

// ---------------------------------------------------------------------------
// Kernel 1: k_pre_mma — UNCHANGED from R12 (proven).
// ---------------------------------------------------------------------------
#define PN_H 0
#define PN_L (128*136)
#define PV_H (2*128*136)
#define PV_L (3*128*136)
#define PW_H (4*128*136)
#define PW_L (5*128*136)
#define P_STAGE PW_H
#define PRE_SMEM (6*128*136*2)   // 208,896 B

__global__ void __launch_bounds__(512, 1) k_pre_mma(
    const float* __restrict__ q_in, const float* __restrict__ v_in,
    const float* __restrict__ ln_g, const float* __restrict__ ln_b,
    const float* __restrict__ bg,   const float* __restrict__ bqk,
    const float* __restrict__ gam,  const float* __restrict__ bet)
{
    extern __shared__ __align__(16) unsigned short sb[];
    const uint32_t sbase = (uint32_t)__cvta_generic_to_shared(sb);

    const int t = threadIdx.x, w = t >> 5, l = t & 31;
    const long g0 = (long)blockIdx.x * 128;
    const int bidx = blockIdx.x >> 5;              // 32 CTAs per batch
    const int s0   = (blockIdx.x & 31) * 128;

    const int l15 = l & 15;
    const int lh  = (l >> 4) << 3;
    const int grp = l >> 3;
    const int brow2 = ((grp >> 1) << 3) + (l & 7);
    const int bcol2 = (grp & 1) << 3;

    const uint4* wqkh4 = (const uint4*)g_WqkT_h;
    const uint4* wqkl4 = (const uint4*)g_WqkT_l;
    const uint4* wgh4  = (const uint4*)g_WgT_h;
    const uint4* wgl4  = (const uint4*)g_WgT_l;

    const int kr = t >> 2, kc = (t & 3) * 4;

    // ---- prefetch Wqk (overlaps phase A) ----
    #pragma unroll
    for (int u = 0; u < 4; ++u) {
        CP16(sbase + 2u*PW_H + (uint32_t)(kr*17 + kc + u)*16,
             (const void*)&wqkh4[kr*16 + kc + u]);
        CP16(sbase + 2u*PW_L + (uint32_t)(kr*17 + kc + u)*16,
             (const void*)&wqkl4[kr*16 + kc + u]);
    }
    CP_COMMIT();

    // ---- Phase A: rope + LN -> nrm hi/lo; val hi/lo (8 tokens per warp) ----
    {
        float f0 = 0.0f, f1 = 0.0f;
        if (l < 8) {
            f0 = powf(10000.0f, -(float)(4 * l)     / 32.0f);
            f1 = powf(10000.0f, -(float)(4 * l + 2) / 32.0f);
        }
        for (int u = 0; u < 8; ++u) {
            const int tok = w * 8 + u;
            const long g = g0 + tok;
            const int s = (int)(g & (SS - 1));

            float4 x = reinterpret_cast<const float4*>(q_in)[g * 32 + l];
            if (l < 8) {
                float s0f, c0f, s1f, c1f;
                sincosf((float)s * f0, &s0f, &c0f);
                sincosf((float)s * f1, &s1f, &c1f);
                float a = x.x, b2 = x.y;
                x.x = a * c0f - b2 * s0f;  x.y = b2 * c0f + a * s0f;
                a = x.z;  b2 = x.w;
                x.z = a * c1f - b2 * s1f;  x.w = b2 * c1f + a * s1f;
            }
            float sum = x.x + x.y + x.z + x.w;
            float sq  = x.x*x.x + x.y*x.y + x.z*x.z + x.w*x.w;
            #pragma unroll
            for (int o = 16; o > 0; o >>= 1) {
                sum += __shfl_xor_sync(0xffffffffu, sum, o);
                sq  += __shfl_xor_sync(0xffffffffu, sq,  o);
            }
            const float mu  = sum * (1.0f / 128.0f);
            const float var = sq  * (1.0f / 128.0f) - mu * mu;
            const float rs  = rsqrtf(var + 1e-5f);

            const int d0 = 4 * l;
            float n0 = (x.x - mu) * rs * ln_g[d0 + 0] + ln_b[d0 + 0];
            float n1 = (x.y - mu) * rs * ln_g[d0 + 1] + ln_b[d0 + 1];
            float n2 = (x.z - mu) * rs * ln_g[d0 + 2] + ln_b[d0 + 2];
            float n3 = (x.w - mu) * rs * ln_g[d0 + 3] + ln_b[d0 + 3];

            unsigned short h0,l0,h1,l1,h2,l2,h3,l3;
            bsplit(n0,h0,l0); bsplit(n1,h1,l1); bsplit(n2,h2,l2); bsplit(n3,h3,l3);
            *(uint2*)(sb + PN_H + tok*136 + d0) =
                make_uint2((uint32_t)h0|((uint32_t)h1<<16), (uint32_t)h2|((uint32_t)h3<<16));
            *(uint2*)(sb + PN_L + tok*136 + d0) =
                make_uint2((uint32_t)l0|((uint32_t)l1<<16), (uint32_t)l2|((uint32_t)l3<<16));

            const float4 vx = reinterpret_cast<const float4*>(v_in)[g * 32 + l];
            bsplit(vx.x,h0,l0); bsplit(vx.y,h1,l1); bsplit(vx.z,h2,l2); bsplit(vx.w,h3,l3);
            *(uint2*)(sb + PV_H + tok*136 + d0) =
                make_uint2((uint32_t)h0|((uint32_t)h1<<16), (uint32_t)h2|((uint32_t)h3<<16));
            *(uint2*)(sb + PV_L + tok*136 + d0) =
                make_uint2((uint32_t)l0|((uint32_t)l1<<16), (uint32_t)l2|((uint32_t)l3<<16));
        }
    }
    CP_WAIT(0);
    __syncthreads();

    // ---- GEMM1: qk = nrm @ WqkT (16 warps, 32x32 tiles, 3-MMA split) ----
    {
        const int rm = (w >> 2) * 32, cn = (w & 3) * 32;
        float s[2][4][4];
        #pragma unroll
        for (int mi = 0; mi < 2; ++mi)
            #pragma unroll
            for (int ni = 0; ni < 4; ++ni)
                #pragma unroll
                for (int q2 = 0; q2 < 4; ++q2) s[mi][ni][q2] = 0.0f;

        #pragma unroll
        for (int kk = 0; kk < 8; ++kk) {
            const int k0 = kk * 16;
            uint32_t a0h[4], a1h[4], a0l[4], a1l[4], bb[8];
            LDSM4(a0h[0],a0h[1],a0h[2],a0h[3], sbase + 2u*(PN_H + (rm+l15)*136 + k0 + lh));
            LDSM4(a1h[0],a1h[1],a1h[2],a1h[3], sbase + 2u*(PN_H + (rm+16+l15)*136 + k0 + lh));
            LDSM4(a0l[0],a0l[1],a0l[2],a0l[3], sbase + 2u*(PN_L + (rm+l15)*136 + k0 + lh));
            LDSM4(a1l[0],a1l[1],a1l[2],a1l[3], sbase + 2u*(PN_L + (rm+16+l15)*136 + k0 + lh));
            LDSM4(bb[0],bb[1],bb[2],bb[3], sbase + 2u*(PW_H + (cn+brow2)*136 + k0 + bcol2));
            LDSM4(bb[4],bb[5],bb[6],bb[7], sbase + 2u*(PW_H + (cn+16+brow2)*136 + k0 + bcol2));
            #pragma unroll
            for (int ni = 0; ni < 4; ++ni) {
                MMABF16(s[0][ni], a0h[0],a0h[1],a0h[2],a0h[3], bb[2*ni], bb[2*ni+1]);
                MMABF16(s[1][ni], a1h[0],a1h[1],a1h[2],a1h[3], bb[2*ni], bb[2*ni+1]);
            }
            #pragma unroll
            for (int ni = 0; ni < 4; ++ni) {
                MMABF16(s[0][ni], a0l[0],a0l[1],a0l[2],a0l[3], bb[2*ni], bb[2*ni+1]);
                MMABF16(s[1][ni], a1l[0],a1l[1],a1l[2],a1l[3], bb[2*ni], bb[2*ni+1]);
            }
            LDSM4(bb[0],bb[1],bb[2],bb[3], sbase + 2u*(PW_L + (cn+brow2)*136 + k0 + bcol2));
            LDSM4(bb[4],bb[5],bb[6],bb[7], sbase + 2u*(PW_L + (cn+16+brow2)*136 + k0 + bcol2));
            #pragma unroll
            for (int ni = 0; ni < 4; ++ni) {
                MMABF16(s[0][ni], a0h[0],a0h[1],a0h[2],a0h[3], bb[2*ni], bb[2*ni+1]);
                MMABF16(s[1][ni], a1h[0],a1h[1],a1h[2],a1h[3], bb[2*ni], bb[2*ni+1]);
            }
        }
        __syncthreads();   // PW free

        // prefetch Wg half0 (overlaps GEMM1 epilogue)
        #pragma unroll
        for (int u = 0; u < 4; ++u) {
            CP16(sbase + 2u*PW_H + (uint32_t)(kr*17 + kc + u)*16,
                 (const void*)&wgh4[kr*16 + kc + u]);
            CP16(sbase + 2u*PW_L + (uint32_t)(kr*17 + kc + u)*16,
                 (const void*)&wgl4[kr*16 + kc + u]);
        }
        CP_COMMIT();

        // epilogue: silu, gamma/beta, fp16 q/k STG
        #pragma unroll
        for (int mi = 0; mi < 2; ++mi) {
            #pragma unroll
            for (int ni = 0; ni < 4; ++ni) {
                const int c = cn + ni * 8 + 2 * (l & 3);
                #pragma unroll
                for (int rr = 0; rr < 2; ++rr) {
                    const int r = rm + mi * 16 + (l >> 2) + rr * 8;
                    const long g = g0 + r;
                    const float v0 = s[mi][ni][2*rr + 0], v1 = s[mi][ni][2*rr + 1];
                    const float sl0 = silu_f(v0 + bqk[c]);
                    const float sl1 = silu_f(v1 + bqk[c + 1]);
                    const unsigned short q0 =
                        __half_as_ushort(__float2half_rn(sl0 * gam[c] + bet[c]));
                    const unsigned short q1 =
                        __half_as_ushort(__float2half_rn(sl1 * gam[c + 1] + bet[c + 1]));
                    const unsigned short k0v =
                        __half_as_ushort(__float2half_rn(sl0 * gam[128 + c] + bet[128 + c]));
                    const unsigned short k1v =
                        __half_as_ushort(__float2half_rn(sl1 * gam[128 + c + 1] + bet[128 + c + 1]));
                    *(uint32_t*)&g_qf[g * 128 + c] = (uint32_t)q0 | ((uint32_t)q1 << 16);
                    *(uint32_t*)&g_kf[g * 128 + c] = (uint32_t)k0v | ((uint32_t)k1v << 16);
                }
            }
        }
    }
    CP_WAIT(0);
    __syncthreads();

    // ---- GEMM2: two h-halves; warps 0-7 gate (A=nrm), 8-15 v (A=val) ----
    for (int hb = 0; hb < 2; ++hb) {
        const int hbase = hb * 128;
        const uint32_t APH = (w < 8) ? (uint32_t)PN_H : (uint32_t)PV_H;
        const uint32_t APL = (w < 8) ? (uint32_t)PN_L : (uint32_t)PV_L;
        const int wl = w & 7;
        const int rm = (wl & 3) * 32, cn = (wl >> 2) * 64;

        float s[2][8][4];
        #pragma unroll
        for (int mi = 0; mi < 2; ++mi)
            #pragma unroll
            for (int ni = 0; ni < 8; ++ni)
                #pragma unroll
                for (int q2 = 0; q2 < 4; ++q2) s[mi][ni][q2] = 0.0f;

        #pragma unroll
        for (int kk = 0; kk < 8; ++kk) {
            const int k0 = kk * 16;
            uint32_t a0h[4], a1h[4], a0l[4], a1l[4], bb[16];
            LDSM4(a0h[0],a0h[1],a0h[2],a0h[3], sbase + 2u*(APH + (rm+l15)*136 + k0 + lh));
            LDSM4(a1h[0],a1h[1],a1h[2],a1h[3], sbase + 2u*(APH + (rm+16+l15)*136 + k0 + lh));
            LDSM4(a0l[0],a0l[1],a0l[2],a0l[3], sbase + 2u*(APL + (rm+l15)*136 + k0 + lh));
            LDSM4(a1l[0],a1l[1],a1l[2],a1l[3], sbase + 2u*(APL + (rm+16+l15)*136 + k0 + lh));
            #pragma unroll
            for (int hp = 0; hp < 4; ++hp)
                LDSM4(bb[4*hp],bb[4*hp+1],bb[4*hp+2],bb[4*hp+3],
                      sbase + 2u*(PW_H + (cn + hp*16 + brow2)*136 + k0 + bcol2));
            #pragma unroll
            for (int ni = 0; ni < 8; ++ni) {
                MMABF16(s[0][ni], a0h[0],a0h[1],a0h[2],a0h[3], bb[2*ni], bb[2*ni+1]);
                MMABF16(s[1][ni], a1h[0],a1h[1],a1h[2],a1h[3], bb[2*ni], bb[2*ni+1]);
            }
            #pragma unroll
            for (int ni = 0; ni < 8; ++ni) {
                MMABF16(s[0][ni], a0l[0],a0l[1],a0l[2],a0l[3], bb[2*ni], bb[2*ni+1]);
                MMABF16(s[1][ni], a1l[0],a1l[1],a1l[2],a1l[3], bb[2*ni], bb[2*ni+1]);
            }
            #pragma unroll
            for (int hp = 0; hp < 4; ++hp)
                LDSM4(bb[4*hp],bb[4*hp+1],bb[4*hp+2],bb[4*hp+3],
                      sbase + 2u*(PW_L + (cn + hp*16 + brow2)*136 + k0 + bcol2));
            #pragma unroll
            for (int ni = 0; ni < 8; ++ni) {
                MMABF16(s[0][ni], a0h[0],a0h[1],a0h[2],a0h[3], bb[2*ni], bb[2*ni+1]);
                MMABF16(s[1][ni], a1h[0],a1h[1],a1h[2],a1h[3], bb[2*ni], bb[2*ni+1]);
            }
        }
        __syncthreads();   // PW readers done -> staging may reuse it

        // epilogue: bias + silu; gate -> STG fp32; v -> fp16 staging (STS)
        #pragma unroll
        for (int mi = 0; mi < 2; ++mi) {
            #pragma unroll
            for (int ni = 0; ni < 8; ++ni) {
                const int c = cn + ni * 8 + 2 * (l & 3);
                const float bb0 = bg[hbase + c], bb1 = bg[hbase + c + 1];
                #pragma unroll
                for (int rr = 0; rr < 2; ++rr) {
                    const int r = rm + mi * 16 + (l >> 2) + rr * 8;
                    const float y0 = silu_f(s[mi][ni][2*rr + 0] + bb0);
                    const float y1 = silu_f(s[mi][ni][2*rr + 1] + bb1);
                    if (w < 8) {
                        *(float2*)&g_gate[(g0 + r) * 256 + hbase + c] = make_float2(y0, y1);
                    } else {
                        sb[P_STAGE + c * 136 + r]       = __half_as_ushort(__float2half_rn(y0));
                        sb[P_STAGE + (c + 1) * 136 + r] = __half_as_ushort(__float2half_rn(y1));
                    }
                }
            }
        }
        __syncthreads();   // staging complete

        // coalesced v copy-out: staging [h 128][tok 128] -> g_vf [b][h][s]
        {
            uint4* gvf4 = (uint4*)g_vf;
            for (int i = t; i < 128 * 16; i += 512) {
                const int hrow = i >> 4, c16 = i & 15;
                const uint4 vv = *(const uint4*)(sb + P_STAGE + hrow * 136 + c16 * 8);
                gvf4[((size_t)bidx * HH + hbase + hrow) * (SS / 8) + (s0 >> 3) + c16] = vv;
            }
        }
        __syncthreads();   // copy-out reads done

        if (hb == 0) {     // load Wg half1
            #pragma unroll
            for (int u = 0; u < 4; ++u) {
                CP16(sbase + 2u*PW_H + (uint32_t)(kr*17 + kc + u)*16,
                     (const void*)&wgh4[(128 + kr)*16 + kc + u]);
                CP16(sbase + 2u*PW_L + (uint32_t)(kr*17 + kc + u)*16,
                     (const void*)&wgl4[(128 + kr)*16 + kc + u]);
            }
            CP_COMMIT();
            CP_WAIT(0);
            __syncthreads();
        }
    }
}

// ---------------------------------------------------------------------------
// Kernel 2: HMMA attention — 64 q-rows/CTA, 256 threads, 8 warps,
// __launch_bounds__(256,2) -> 2 CTAs/SM for cross-CTA phase overlap.
// fp16 single-pass sim + fp16 PV (2^30 scale). k double-buffered cp.async.
// smem: tile region 98,304 B > og region 64*264*4 = 67,584 B.
// ---------------------------------------------------------------------------
#define QS  0
#define KS0 (64*136)
#define KS1 (2*64*136)
#define VS  (3*64*136)
#define AS  (3*64*136 + 256*72)
#define SM_HALVES (AS + 64*72)
#define OGS 264
#define SMEM_BYTES (SM_HALVES*2)       // 98,304 B (covers og: 67,584 B)

__global__ void __launch_bounds__(256, 2) k_attn(
    const float* __restrict__ Wout, const float* __restrict__ bout,
    float* __restrict__ out, float* __restrict__ att)
{
    extern __shared__ __align__(16) unsigned short sb[];

    const int t = threadIdx.x, w = t >> 5, l = t & 31;
    const int b = blockIdx.y, i0 = blockIdx.x * 64;
    const long tbase = (long)b * SS;
    const int rm = (w & 3) * 16, cn = (w >> 2) * 32;    // sim: 4x2 warp grid
    const int pr = (w & 1) * 32, ph = (w >> 1) * 64;    // PV:  2x4 warp grid

    const int l15 = l & 15;
    const int lh  = (l >> 4) << 3;
    const int grp = l >> 3;
    const int brow2 = ((grp >> 1) << 3) + (l & 7);
    const int bcol2 = (grp & 1) << 3;

    const uint32_t sbase = (uint32_t)__cvta_generic_to_shared(sb);

    const uint4* gq4 = (const uint4*)g_qf;
    const uint4* gk4 = (const uint4*)g_kf;
    const uint4* gv4 = (const uint4*)g_vf;

    const int kr = t >> 2, kc = (t & 3) * 4;   // k: 64 rows x 16 uint4, 4/thr
    const int vh = t;                          // v: 256 rows, 1 row (8 uint4)/thr

    // ---- prologue: prefetch k(0) into buf0; load q tile ----
    {
        #pragma unroll
        for (int u = 0; u < 4; ++u)
            CP16(sbase + 2u*KS0 + (uint32_t)(kr*17 + kc + u)*16,
                 (const void*)&gk4[(tbase + kr) * 16 + kc + u]);
        CP_COMMIT();
    }
    for (int i = t; i < 64 * 16; i += 256) {
        const int r = i >> 4, c4 = i & 15;
        ((uint4*)(sb + QS))[r * 17 + c4] = gq4[(tbase + i0 + r) * 16 + c4];
    }

    float o[2][8][4];
    #pragma unroll
    for (int a = 0; a < 2; ++a)
        #pragma unroll
        for (int j = 0; j < 8; ++j)
            #pragma unroll
            for (int c = 0; c < 4; ++c) o[a][j][c] = 0.0f;

    float2* attb2 = (float2*)(att + (size_t)b * SS * SS);
    const float invS = 1.0f / (float)SS;

    for (int it = 0; it < NT; ++it) {
        const int j0 = it * 64;
        const uint32_t ks = (it & 1) ? KS1 : KS0;

        CP_WAIT(0);          // k(it) resident
        __syncthreads();     // k visible; PV(it-1) readers of v/as done

        // prefetch v(it): overlaps sim + convert   [group G1]
        {
            const size_t src = ((size_t)b * HH + vh) * (SS / 8) + (j0 >> 3);
            #pragma unroll
            for (int u = 0; u < 8; ++u)
                CP16(sbase + 2u*VS + (uint32_t)(vh*9 + u)*16,
                     (const void*)&gv4[src + u]);
            CP_COMMIT();
        }
        // prefetch k(it+1) into other buffer [group G2]
        if (it + 1 < NT) {
            const uint32_t nk = (it & 1) ? KS0 : KS1;
            #pragma unroll
            for (int u = 0; u < 4; ++u)
                CP16(sbase + 2u*nk + (uint32_t)(kr*17 + kc + u)*16,
                     (const void*)&gk4[(tbase + j0 + 64 + kr) * 16 + kc + u]);
            CP_COMMIT();
        }

        // ---- sim: rows rm..+15, cols cn..+31, fp16 single-pass ----
        float s[4][4];
        #pragma unroll
        for (int i = 0; i < 4; ++i)
            #pragma unroll
            for (int j = 0; j < 4; ++j) s[i][j] = 0.0f;

        #pragma unroll
        for (int kk = 0; kk < 8; ++kk) {
            const int k0 = kk * 16;
            uint32_t a0, a1, a2, a3, bbv[8];
            LDSM4(a0, a1, a2, a3, sbase + 2u*(QS + (rm + l15)*136 + k0 + lh));
            LDSM4(bbv[0], bbv[1], bbv[2], bbv[3],
                  sbase + 2u*(ks + (cn + brow2)*136 + k0 + bcol2));
            LDSM4(bbv[4], bbv[5], bbv[6], bbv[7],
                  sbase + 2u*(ks + (cn + 16 + brow2)*136 + k0 + bcol2));
            #pragma unroll
            for (int nt = 0; nt < 4; ++nt)
                MMAF16(s[nt], a0, a1, a2, a3, bbv[2*nt], bbv[2*nt+1]);
        }

        // ---- relu^2/S^2 -> att (fp32 global) + as (fp16 * 2^30, smem) ----
        {
            const int ra = rm + (l >> 2);
            const int rb = ra + 8;
            #pragma unroll
            for (int nt = 0; nt < 4; ++nt) {
                const int colg = cn + nt * 8 + 2 * (l & 3);
                float x;
                x = fmaxf(s[nt][0], 0.0f) * invS; const float a0 = x * x;
                x = fmaxf(s[nt][1], 0.0f) * invS; const float a1 = x * x;
                x = fmaxf(s[nt][2], 0.0f) * invS; const float a2 = x * x;
                x = fmaxf(s[nt][3], 0.0f) * invS; const float a3 = x * x;

                attb2[((size_t)(i0 + ra) * SS + j0 + colg) >> 1] = make_float2(a0, a1);
                attb2[((size_t)(i0 + rb) * SS + j0 + colg) >> 1] = make_float2(a2, a3);

                const unsigned short f0 = __half_as_ushort(__float2half_rn(a0 * ASCALE));
                const unsigned short f1 = __half_as_ushort(__float2half_rn(a1 * ASCALE));
                const unsigned short f2 = __half_as_ushort(__float2half_rn(a2 * ASCALE));
                const unsigned short f3 = __half_as_ushort(__float2half_rn(a3 * ASCALE));
                *(uint32_t*)(sb + AS + ra * 72 + colg) = (uint32_t)f0 | ((uint32_t)f1 << 16);
                *(uint32_t*)(sb + AS + rb * 72 + colg) = (uint32_t)f2 | ((uint32_t)f3 << 16);
            }
        }

        if (it + 1 < NT) { CP_WAIT(1); } else { CP_WAIT(0); }  // v(it) done
        __syncthreads();     // as + v visible everywhere

        // ---- PV (fp16): rows pr..+31, h ph..+63 ----
        #pragma unroll
        for (int kt = 0; kt < 4; ++kt) {
            const int tok0 = kt * 16;
            uint32_t A0[4], A1[4], Bv[16];
            LDSM4(A0[0], A0[1], A0[2], A0[3],
                  sbase + 2u*(AS + (pr + l15)*72 + tok0 + lh));
            LDSM4(A1[0], A1[1], A1[2], A1[3],
                  sbase + 2u*(AS + (pr + 16 + l15)*72 + tok0 + lh));
            #pragma unroll
            for (int hp = 0; hp < 4; ++hp)
                LDSM4(Bv[4*hp], Bv[4*hp+1], Bv[4*hp+2], Bv[4*hp+3],
                      sbase + 2u*(VS + (ph + hp*16 + brow2)*72 + tok0 + bcol2));
            #pragma unroll
            for (int j = 0; j < 8; ++j)
                MMAF16(o[0][j], A0[0], A0[1], A0[2], A0[3], Bv[2*j], Bv[2*j+1]);
            #pragma unroll
            for (int j = 0; j < 8; ++j)
                MMAF16(o[1][j], A1[0], A1[1], A1[2], A1[3], Bv[2*j], Bv[2*j+1]);
        }
    }

    // ---- epilogue: og = o * gate * 2^-30 -> smem, then @ W_out + b ----
    __syncthreads();
    float* og = (float*)sb;
    {
        const int ra0 = pr + (l >> 2);
        #pragma unroll
        for (int rg = 0; rg < 2; ++rg) {
            const int ra = ra0 + rg * 16;
            const int rb = ra + 8;
            #pragma unroll
            for (int j = 0; j < 8; ++j) {
                const int hc = ph + (j >> 1) * 16 + (j & 1) * 8 + 2 * (l & 3);
                const float2 ga = *(const float2*)&g_gate[(tbase + i0 + ra) * 256 + hc];
                const float2 gb = *(const float2*)&g_gate[(tbase + i0 + rb) * 256 + hc];
                *(float2*)&og[ra * OGS + hc] =
                    make_float2(o[rg][j][0] * ga.x * INV_ASCALE,
                                o[rg][j][1] * ga.y * INV_ASCALE);
                *(float2*)&og[rb * OGS + hc] =
                    make_float2(o[rg][j][2] * gb.x * INV_ASCALE,
                                o[rg][j][3] * gb.y * INV_ASCALE);
            }
        }
    }
    __syncthreads();

    {
        const int c = t & 127, r0 = t >> 7;        // r0 in {0,1}
        float acc2[32];
        #pragma unroll
        for (int i = 0; i < 32; ++i) acc2[i] = 0.0f;
        for (int h = 0; h < 256; ++h) {
            const float wv = Wout[h * 128 + c];
            #pragma unroll
            for (int i = 0; i < 32; ++i)
                acc2[i] += og[(r0 + 2 * i) * OGS + h] * wv;
        }
        const float bb = bout[c];
        #pragma unroll
        for (int i = 0; i < 32; ++i)
            out[(tbase + i0 + r0 + 2 * i) * 128 + c] = acc2[i] + bb;
    }
}

// ---------------------------------------------------------------------------
extern "C" void kernel_launch(void* const* d_in, const int* in_sizes, int n_in,
                              void* d_out, int out_size)
{
    const float* query = (const float*)d_in[0];
    const float* value = (const float*)d_in[2];
    const float* ln_g  = (const float*)d_in[3];
    const float* ln_b  = (const float*)d_in[4];
    const float* Wg    = (const float*)d_in[5];
    const float* bg    = (const float*)d_in[6];
    const float* Wqk   = (const float*)d_in[7];
    const float* bqk   = (const float*)d_in[8];
    const float* gam   = (const float*)d_in[9];
    const float* bet   = (const float*)d_in[10];
    const float* Wout  = (const float*)d_in[11];
    const float* bout  = (const float*)d_in[12];

    float* out = (float*)d_out;                       // [B,S,D] first
    float* att = out + (size_t)BB * SS * DD;          // then [B,S,S]

    cudaFuncSetAttribute(k_pre_mma, cudaFuncAttributeMaxDynamicSharedMemorySize,
                         PRE_SMEM);
    cudaFuncSetAttribute(k_attn, cudaFuncAttributeMaxDynamicSharedMemorySize,
                         SMEM_BYTES);

    k_wconv<<<(HH * DD) / 256, 256>>>(Wqk, Wg);
    k_pre_mma<<<NTOK / 128, 512, PRE_SMEM>>>(query, value, ln_g, ln_b,
                                             bg, bqk, gam, bet);

    dim3 g2(SS / 64, BB);
    k_attn<<<g2, 256, SMEM_BYTES>>>(Wout, bout, out, att);
}

// round 15
// speedup vs baseline: 1.2083x; 1.2083x over previous
#include <cuda_runtime.h>
#include <cuda_bf16.h>
#include <cuda_fp16.h>
#include <math.h>
#include <stdint.h>

#define BB 4
#define SS 4096
#define DD 128
#define HH 256
#define NTOK (BB*SS)
#define NT (SS/64)

#define ASCALE 1073741824.0f          // 2^30 attn pre-scale for fp16 PV
#define INV_ASCALE (1.0f/1073741824.0f)

// Operands (device globals: allocation-free rule)
__device__ __align__(16) __half g_qf[NTOK*DD];   // [tok][d] fp16
__device__ __align__(16) __half g_kf[NTOK*DD];   // [tok][d] fp16
__device__ __align__(16) __half g_vf[NTOK*HH];   // [b][h][s] fp16
__device__ float g_gate[NTOK*HH];                 // [tok][h] fp32

// Split-bf16 transposed weights (k_pre GEMMs keep full precision)
__device__ __align__(16) __nv_bfloat16 g_WqkT_h[DD*DD]; // [n][k]
__device__ __align__(16) __nv_bfloat16 g_WqkT_l[DD*DD];
__device__ __align__(16) __nv_bfloat16 g_WgT_h[HH*DD];  // [n][k]
__device__ __align__(16) __nv_bfloat16 g_WgT_l[HH*DD];

__device__ __forceinline__ float silu_f(float x) {
    return x / (1.0f + expf(-x));
}

__device__ __forceinline__ void bsplit(float x, unsigned short& hi, unsigned short& lo) {
    __nv_bfloat16 h = __float2bfloat16(x);
    __nv_bfloat16 l = __float2bfloat16(x - __bfloat162float(h));
    hi = __bfloat16_as_ushort(h);
    lo = __bfloat16_as_ushort(l);
}

#define LDSM4(r0, r1, r2, r3, a)                                              \
    asm volatile("ldmatrix.sync.aligned.m8n8.x4.shared.b16 {%0,%1,%2,%3},[%4];" \
                 : "=r"(r0), "=r"(r1), "=r"(r2), "=r"(r3) : "r"(a));

#define MMABF16(d, a0, a1, a2, a3, b0, b1)                                    \
    asm volatile("mma.sync.aligned.m16n8k16.row.col.f32.bf16.bf16.f32 "       \
                 "{%0,%1,%2,%3},{%4,%5,%6,%7},{%8,%9},{%0,%1,%2,%3};"         \
                 : "+f"(d[0]), "+f"(d[1]), "+f"(d[2]), "+f"(d[3])             \
                 : "r"(a0), "r"(a1), "r"(a2), "r"(a3), "r"(b0), "r"(b1));

#define MMAF16(d, a0, a1, a2, a3, b0, b1)                                     \
    asm volatile("mma.sync.aligned.m16n8k16.row.col.f32.f16.f16.f32 "         \
                 "{%0,%1,%2,%3},{%4,%5,%6,%7},{%8,%9},{%0,%1,%2,%3};"         \
                 : "+f"(d[0]), "+f"(d[1]), "+f"(d[2]), "+f"(d[3])             \
                 : "r"(a0), "r"(a1), "r"(a2), "r"(a3), "r"(b0), "r"(b1));

#define CP16(dst, src) \
    asm volatile("cp.async.cg.shared.global [%0], [%1], 16;" \
                 :: "r"(dst), "l"(src) : "memory")
#define CP_COMMIT() asm volatile("cp.async.commit_group;" ::: "memory")
#define CP_WAIT(n)  asm volatile("cp.async.wait_group %0;" :: "n"(n) : "memory")

// ---------------------------------------------------------------------------
// Kernel 0: weight transpose + split-bf16 conversion (tiny).
// ---------------------------------------------------------------------------
__global__ void __launch_bounds__(256) k_wconv(
    const float* __restrict__ Wqk, const float* __restrict__ Wg)
{
    const int i = blockIdx.x * 256 + threadIdx.x;
    unsigned short hi, lo;
    if (i < DD * DD) {
        const int n = i >> 7, k = i & 127;
        bsplit(Wqk[k * DD + n], hi, lo);
        g_WqkT_h[i] = __ushort_as_bfloat16(hi);
        g_WqkT_l[i] = __ushort_as_bfloat16(lo);
    }
    if (i < HH * DD) {
        const int n = i >> 7, k = i & 127;
        bsplit(Wg[k * HH + n], hi, lo);
        g_WgT_h[i] = __ushort_as_bfloat16(hi);
        g_WgT_l[i] = __ushort_as_bfloat16(lo);
    }
}

// ---------------------------------------------------------------------------
// Kernel 1: k_pre_mma — UNCHANGED from R12 (proven).
// ---------------------------------------------------------------------------
#define PN_H 0
#define PN_L (128*136)
#define PV_H (2*128*136)
#define PV_L (3*128*136)
#define PW_H (4*128*136)
#define PW_L (5*128*136)
#define P_STAGE PW_H
#define PRE_SMEM (6*128*136*2)   // 208,896 B

__global__ void __launch_bounds__(512, 1) k_pre_mma(
    const float* __restrict__ q_in, const float* __restrict__ v_in,
    const float* __restrict__ ln_g, const float* __restrict__ ln_b,
    const float* __restrict__ bg,   const float* __restrict__ bqk,
    const float* __restrict__ gam,  const float* __restrict__ bet)
{
    extern __shared__ __align__(16) unsigned short sb[];
    const uint32_t sbase = (uint32_t)__cvta_generic_to_shared(sb);

    const int t = threadIdx.x, w = t >> 5, l = t & 31;
    const long g0 = (long)blockIdx.x * 128;
    const int bidx = blockIdx.x >> 5;              // 32 CTAs per batch
    const int s0   = (blockIdx.x & 31) * 128;

    const int l15 = l & 15;
    const int lh  = (l >> 4) << 3;
    const int grp = l >> 3;
    const int brow2 = ((grp >> 1) << 3) + (l & 7);
    const int bcol2 = (grp & 1) << 3;

    const uint4* wqkh4 = (const uint4*)g_WqkT_h;
    const uint4* wqkl4 = (const uint4*)g_WqkT_l;
    const uint4* wgh4  = (const uint4*)g_WgT_h;
    const uint4* wgl4  = (const uint4*)g_WgT_l;

    const int kr = t >> 2, kc = (t & 3) * 4;

    // ---- prefetch Wqk (overlaps phase A) ----
    #pragma unroll
    for (int u = 0; u < 4; ++u) {
        CP16(sbase + 2u*PW_H + (uint32_t)(kr*17 + kc + u)*16,
             (const void*)&wqkh4[kr*16 + kc + u]);
        CP16(sbase + 2u*PW_L + (uint32_t)(kr*17 + kc + u)*16,
             (const void*)&wqkl4[kr*16 + kc + u]);
    }
    CP_COMMIT();

    // ---- Phase A: rope + LN -> nrm hi/lo; val hi/lo (8 tokens per warp) ----
    {
        float f0 = 0.0f, f1 = 0.0f;
        if (l < 8) {
            f0 = powf(10000.0f, -(float)(4 * l)     / 32.0f);
            f1 = powf(10000.0f, -(float)(4 * l + 2) / 32.0f);
        }
        for (int u = 0; u < 8; ++u) {
            const int tok = w * 8 + u;
            const long g = g0 + tok;
            const int s = (int)(g & (SS - 1));

            float4 x = reinterpret_cast<const float4*>(q_in)[g * 32 + l];
            if (l < 8) {
                float s0f, c0f, s1f, c1f;
                sincosf((float)s * f0, &s0f, &c0f);
                sincosf((float)s * f1, &s1f, &c1f);
                float a = x.x, b2 = x.y;
                x.x = a * c0f - b2 * s0f;  x.y = b2 * c0f + a * s0f;
                a = x.z;  b2 = x.w;
                x.z = a * c1f - b2 * s1f;  x.w = b2 * c1f + a * s1f;
            }
            float sum = x.x + x.y + x.z + x.w;
            float sq  = x.x*x.x + x.y*x.y + x.z*x.z + x.w*x.w;
            #pragma unroll
            for (int o = 16; o > 0; o >>= 1) {
                sum += __shfl_xor_sync(0xffffffffu, sum, o);
                sq  += __shfl_xor_sync(0xffffffffu, sq,  o);
            }
            const float mu  = sum * (1.0f / 128.0f);
            const float var = sq  * (1.0f / 128.0f) - mu * mu;
            const float rs  = rsqrtf(var + 1e-5f);

            const int d0 = 4 * l;
            float n0 = (x.x - mu) * rs * ln_g[d0 + 0] + ln_b[d0 + 0];
            float n1 = (x.y - mu) * rs * ln_g[d0 + 1] + ln_b[d0 + 1];
            float n2 = (x.z - mu) * rs * ln_g[d0 + 2] + ln_b[d0 + 2];
            float n3 = (x.w - mu) * rs * ln_g[d0 + 3] + ln_b[d0 + 3];

            unsigned short h0,l0,h1,l1,h2,l2,h3,l3;
            bsplit(n0,h0,l0); bsplit(n1,h1,l1); bsplit(n2,h2,l2); bsplit(n3,h3,l3);
            *(uint2*)(sb + PN_H + tok*136 + d0) =
                make_uint2((uint32_t)h0|((uint32_t)h1<<16), (uint32_t)h2|((uint32_t)h3<<16));
            *(uint2*)(sb + PN_L + tok*136 + d0) =
                make_uint2((uint32_t)l0|((uint32_t)l1<<16), (uint32_t)l2|((uint32_t)l3<<16));

            const float4 vx = reinterpret_cast<const float4*>(v_in)[g * 32 + l];
            bsplit(vx.x,h0,l0); bsplit(vx.y,h1,l1); bsplit(vx.z,h2,l2); bsplit(vx.w,h3,l3);
            *(uint2*)(sb + PV_H + tok*136 + d0) =
                make_uint2((uint32_t)h0|((uint32_t)h1<<16), (uint32_t)h2|((uint32_t)h3<<16));
            *(uint2*)(sb + PV_L + tok*136 + d0) =
                make_uint2((uint32_t)l0|((uint32_t)l1<<16), (uint32_t)l2|((uint32_t)l3<<16));
        }
    }
    CP_WAIT(0);
    __syncthreads();

    // ---- GEMM1: qk = nrm @ WqkT (16 warps, 32x32 tiles, 3-MMA split) ----
    {
        const int rm = (w >> 2) * 32, cn = (w & 3) * 32;
        float s[2][4][4];
        #pragma unroll
        for (int mi = 0; mi < 2; ++mi)
            #pragma unroll
            for (int ni = 0; ni < 4; ++ni)
                #pragma unroll
                for (int q2 = 0; q2 < 4; ++q2) s[mi][ni][q2] = 0.0f;

        #pragma unroll
        for (int kk = 0; kk < 8; ++kk) {
            const int k0 = kk * 16;
            uint32_t a0h[4], a1h[4], a0l[4], a1l[4], bb[8];
            LDSM4(a0h[0],a0h[1],a0h[2],a0h[3], sbase + 2u*(PN_H + (rm+l15)*136 + k0 + lh));
            LDSM4(a1h[0],a1h[1],a1h[2],a1h[3], sbase + 2u*(PN_H + (rm+16+l15)*136 + k0 + lh));
            LDSM4(a0l[0],a0l[1],a0l[2],a0l[3], sbase + 2u*(PN_L + (rm+l15)*136 + k0 + lh));
            LDSM4(a1l[0],a1l[1],a1l[2],a1l[3], sbase + 2u*(PN_L + (rm+16+l15)*136 + k0 + lh));
            LDSM4(bb[0],bb[1],bb[2],bb[3], sbase + 2u*(PW_H + (cn+brow2)*136 + k0 + bcol2));
            LDSM4(bb[4],bb[5],bb[6],bb[7], sbase + 2u*(PW_H + (cn+16+brow2)*136 + k0 + bcol2));
            #pragma unroll
            for (int ni = 0; ni < 4; ++ni) {
                MMABF16(s[0][ni], a0h[0],a0h[1],a0h[2],a0h[3], bb[2*ni], bb[2*ni+1]);
                MMABF16(s[1][ni], a1h[0],a1h[1],a1h[2],a1h[3], bb[2*ni], bb[2*ni+1]);
            }
            #pragma unroll
            for (int ni = 0; ni < 4; ++ni) {
                MMABF16(s[0][ni], a0l[0],a0l[1],a0l[2],a0l[3], bb[2*ni], bb[2*ni+1]);
                MMABF16(s[1][ni], a1l[0],a1l[1],a1l[2],a1l[3], bb[2*ni], bb[2*ni+1]);
            }
            LDSM4(bb[0],bb[1],bb[2],bb[3], sbase + 2u*(PW_L + (cn+brow2)*136 + k0 + bcol2));
            LDSM4(bb[4],bb[5],bb[6],bb[7], sbase + 2u*(PW_L + (cn+16+brow2)*136 + k0 + bcol2));
            #pragma unroll
            for (int ni = 0; ni < 4; ++ni) {
                MMABF16(s[0][ni], a0h[0],a0h[1],a0h[2],a0h[3], bb[2*ni], bb[2*ni+1]);
                MMABF16(s[1][ni], a1h[0],a1h[1],a1h[2],a1h[3], bb[2*ni], bb[2*ni+1]);
            }
        }
        __syncthreads();   // PW free

        // prefetch Wg half0 (overlaps GEMM1 epilogue)
        #pragma unroll
        for (int u = 0; u < 4; ++u) {
            CP16(sbase + 2u*PW_H + (uint32_t)(kr*17 + kc + u)*16,
                 (const void*)&wgh4[kr*16 + kc + u]);
            CP16(sbase + 2u*PW_L + (uint32_t)(kr*17 + kc + u)*16,
                 (const void*)&wgl4[kr*16 + kc + u]);
        }
        CP_COMMIT();

        // epilogue: silu, gamma/beta, fp16 q/k STG
        #pragma unroll
        for (int mi = 0; mi < 2; ++mi) {
            #pragma unroll
            for (int ni = 0; ni < 4; ++ni) {
                const int c = cn + ni * 8 + 2 * (l & 3);
                #pragma unroll
                for (int rr = 0; rr < 2; ++rr) {
                    const int r = rm + mi * 16 + (l >> 2) + rr * 8;
                    const long g = g0 + r;
                    const float v0 = s[mi][ni][2*rr + 0], v1 = s[mi][ni][2*rr + 1];
                    const float sl0 = silu_f(v0 + bqk[c]);
                    const float sl1 = silu_f(v1 + bqk[c + 1]);
                    const unsigned short q0 =
                        __half_as_ushort(__float2half_rn(sl0 * gam[c] + bet[c]));
                    const unsigned short q1 =
                        __half_as_ushort(__float2half_rn(sl1 * gam[c + 1] + bet[c + 1]));
                    const unsigned short k0v =
                        __half_as_ushort(__float2half_rn(sl0 * gam[128 + c] + bet[128 + c]));
                    const unsigned short k1v =
                        __half_as_ushort(__float2half_rn(sl1 * gam[128 + c + 1] + bet[128 + c + 1]));
                    *(uint32_t*)&g_qf[g * 128 + c] = (uint32_t)q0 | ((uint32_t)q1 << 16);
                    *(uint32_t*)&g_kf[g * 128 + c] = (uint32_t)k0v | ((uint32_t)k1v << 16);
                }
            }
        }
    }
    CP_WAIT(0);
    __syncthreads();

    // ---- GEMM2: two h-halves; warps 0-7 gate (A=nrm), 8-15 v (A=val) ----
    for (int hb = 0; hb < 2; ++hb) {
        const int hbase = hb * 128;
        const uint32_t APH = (w < 8) ? (uint32_t)PN_H : (uint32_t)PV_H;
        const uint32_t APL = (w < 8) ? (uint32_t)PN_L : (uint32_t)PV_L;
        const int wl = w & 7;
        const int rm = (wl & 3) * 32, cn = (wl >> 2) * 64;

        float s[2][8][4];
        #pragma unroll
        for (int mi = 0; mi < 2; ++mi)
            #pragma unroll
            for (int ni = 0; ni < 8; ++ni)
                #pragma unroll
                for (int q2 = 0; q2 < 4; ++q2) s[mi][ni][q2] = 0.0f;

        #pragma unroll
        for (int kk = 0; kk < 8; ++kk) {
            const int k0 = kk * 16;
            uint32_t a0h[4], a1h[4], a0l[4], a1l[4], bb[16];
            LDSM4(a0h[0],a0h[1],a0h[2],a0h[3], sbase + 2u*(APH + (rm+l15)*136 + k0 + lh));
            LDSM4(a1h[0],a1h[1],a1h[2],a1h[3], sbase + 2u*(APH + (rm+16+l15)*136 + k0 + lh));
            LDSM4(a0l[0],a0l[1],a0l[2],a0l[3], sbase + 2u*(APL + (rm+l15)*136 + k0 + lh));
            LDSM4(a1l[0],a1l[1],a1l[2],a1l[3], sbase + 2u*(APL + (rm+16+l15)*136 + k0 + lh));
            #pragma unroll
            for (int hp = 0; hp < 4; ++hp)
                LDSM4(bb[4*hp],bb[4*hp+1],bb[4*hp+2],bb[4*hp+3],
                      sbase + 2u*(PW_H + (cn + hp*16 + brow2)*136 + k0 + bcol2));
            #pragma unroll
            for (int ni = 0; ni < 8; ++ni) {
                MMABF16(s[0][ni], a0h[0],a0h[1],a0h[2],a0h[3], bb[2*ni], bb[2*ni+1]);
                MMABF16(s[1][ni], a1h[0],a1h[1],a1h[2],a1h[3], bb[2*ni], bb[2*ni+1]);
            }
            #pragma unroll
            for (int ni = 0; ni < 8; ++ni) {
                MMABF16(s[0][ni], a0l[0],a0l[1],a0l[2],a0l[3], bb[2*ni], bb[2*ni+1]);
                MMABF16(s[1][ni], a1l[0],a1l[1],a1l[2],a1l[3], bb[2*ni], bb[2*ni+1]);
            }
            #pragma unroll
            for (int hp = 0; hp < 4; ++hp)
                LDSM4(bb[4*hp],bb[4*hp+1],bb[4*hp+2],bb[4*hp+3],
                      sbase + 2u*(PW_L + (cn + hp*16 + brow2)*136 + k0 + bcol2));
            #pragma unroll
            for (int ni = 0; ni < 8; ++ni) {
                MMABF16(s[0][ni], a0h[0],a0h[1],a0h[2],a0h[3], bb[2*ni], bb[2*ni+1]);
                MMABF16(s[1][ni], a1h[0],a1h[1],a1h[2],a1h[3], bb[2*ni], bb[2*ni+1]);
            }
        }
        __syncthreads();   // PW readers done -> staging may reuse it

        // epilogue: bias + silu; gate -> STG fp32; v -> fp16 staging (STS)
        #pragma unroll
        for (int mi = 0; mi < 2; ++mi) {
            #pragma unroll
            for (int ni = 0; ni < 8; ++ni) {
                const int c = cn + ni * 8 + 2 * (l & 3);
                const float bb0 = bg[hbase + c], bb1 = bg[hbase + c + 1];
                #pragma unroll
                for (int rr = 0; rr < 2; ++rr) {
                    const int r = rm + mi * 16 + (l >> 2) + rr * 8;
                    const float y0 = silu_f(s[mi][ni][2*rr + 0] + bb0);
                    const float y1 = silu_f(s[mi][ni][2*rr + 1] + bb1);
                    if (w < 8) {
                        *(float2*)&g_gate[(g0 + r) * 256 + hbase + c] = make_float2(y0, y1);
                    } else {
                        sb[P_STAGE + c * 136 + r]       = __half_as_ushort(__float2half_rn(y0));
                        sb[P_STAGE + (c + 1) * 136 + r] = __half_as_ushort(__float2half_rn(y1));
                    }
                }
            }
        }
        __syncthreads();   // staging complete

        // coalesced v copy-out: staging [h 128][tok 128] -> g_vf [b][h][s]
        {
            uint4* gvf4 = (uint4*)g_vf;
            for (int i = t; i < 128 * 16; i += 512) {
                const int hrow = i >> 4, c16 = i & 15;
                const uint4 vv = *(const uint4*)(sb + P_STAGE + hrow * 136 + c16 * 8);
                gvf4[((size_t)bidx * HH + hbase + hrow) * (SS / 8) + (s0 >> 3) + c16] = vv;
            }
        }
        __syncthreads();   // copy-out reads done

        if (hb == 0) {     // load Wg half1
            #pragma unroll
            for (int u = 0; u < 4; ++u) {
                CP16(sbase + 2u*PW_H + (uint32_t)(kr*17 + kc + u)*16,
                     (const void*)&wgh4[(128 + kr)*16 + kc + u]);
                CP16(sbase + 2u*PW_L + (uint32_t)(kr*17 + kc + u)*16,
                     (const void*)&wgl4[(128 + kr)*16 + kc + u]);
            }
            CP_COMMIT();
            CP_WAIT(0);
            __syncthreads();
        }
    }
}

// ---------------------------------------------------------------------------
// Kernel 2: HMMA attention — software-pipelined. 128 q-rows/CTA, 512 thr.
// Per iter (ONE barrier): wait{k(it),v(it-1)} -> sync -> prefetch{v(it),
// k(it+1)} -> PV(it-1)[as/v buf (it-1)&1] -> sim(it) -> convert->as buf it&1.
// fp16 single-pass sim + fp16 PV (2^30 scale). as/v/k all double-buffered.
// ---------------------------------------------------------------------------
#define QS  0
#define KS0 (128*136)
#define KS1 (KS0 + 64*136)
#define VS0 (KS1 + 64*136)
#define VS1 (VS0 + 256*72)
#define AS0 (VS1 + 256*72)
#define AS1 (AS0 + 128*72)
#define SM_HALVES (AS1 + 128*72)
#define OGS 264
#define OG_BYTES (128*OGS*4)           // 135,168 B
#define SMEM_BYTES (SM_HALVES*2)       // 180,224 B (> OG_BYTES)

__global__ void __launch_bounds__(512, 1) k_attn(
    const float* __restrict__ Wout, const float* __restrict__ bout,
    float* __restrict__ out, float* __restrict__ att)
{
    extern __shared__ __align__(16) unsigned short sb[];

    const int t = threadIdx.x, w = t >> 5, l = t & 31;
    const int b = blockIdx.y, i0 = blockIdx.x * 128;
    const long tbase = (long)b * SS;
    const int wm = w & 7, wh = w >> 3;          // sim mapping
    const int rm = wm * 16, cn = wh * 32;
    const int wr = w & 3, wc = w >> 2;          // PV mapping
    const int pr = wr * 32, ph = wc * 64;

    const int l15 = l & 15;
    const int lh  = (l >> 4) << 3;
    const int grp = l >> 3;
    const int brow2 = ((grp >> 1) << 3) + (l & 7);
    const int bcol2 = (grp & 1) << 3;

    const uint32_t sbase = (uint32_t)__cvta_generic_to_shared(sb);

    const uint4* gq4 = (const uint4*)g_qf;
    const uint4* gk4 = (const uint4*)g_kf;
    const uint4* gv4 = (const uint4*)g_vf;

    const int kr = t >> 3, kc = (t & 7) * 2;     // k: 64 rows x 16 uint4
    const int vh = t >> 1, vc = (t & 1) * 4;     // v: 256 rows x 8 uint4

    // ---- prologue: prefetch k(0) into KS0; load q tile ----
    {
        CP16(sbase + 2u*KS0 + (uint32_t)(kr*17 + kc    )*16,
             (const void*)&gk4[(tbase + kr) * 16 + kc]);
        CP16(sbase + 2u*KS0 + (uint32_t)(kr*17 + kc + 1)*16,
             (const void*)&gk4[(tbase + kr) * 16 + kc + 1]);
        CP_COMMIT();
    }
    for (int i = t; i < 128 * 16; i += 512) {
        const int r = i >> 4, c4 = i & 15;
        ((uint4*)(sb + QS))[r * 17 + c4] = gq4[(tbase + i0 + r) * 16 + c4];
    }

    float o[2][8][4];
    #pragma unroll
    for (int a = 0; a < 2; ++a)
        #pragma unroll
        for (int j = 0; j < 8; ++j)
            #pragma unroll
            for (int c = 0; c < 4; ++c) o[a][j][c] = 0.0f;

    float2* attb2 = (float2*)(att + (size_t)b * SS * SS);
    const float invS = 1.0f / (float)SS;

    for (int it = 0; it < NT; ++it) {
        const int j0 = it * 64;
        const uint32_t ks   = (it & 1) ? KS1 : KS0;
        const uint32_t vs_c = (it & 1) ? VS1 : VS0;   // v(it) dest
        const uint32_t as_c = (it & 1) ? AS1 : AS0;   // as(it) dest
        const uint32_t vs_p = (it & 1) ? VS0 : VS1;   // v(it-1) src
        const uint32_t as_p = (it & 1) ? AS0 : AS1;   // as(it-1) src

        CP_WAIT(0);          // {k(it), v(it-1)} resident
        __syncthreads();     // publish as(it-1) writes + cp.async data

        // prefetch v(it) + k(it+1) as one group, waited at next iter head
        {
            const size_t src = ((size_t)b * HH + vh) * (SS / 8) + (j0 >> 3) + vc;
            #pragma unroll
            for (int u = 0; u < 4; ++u)
                CP16(sbase + 2u*vs_c + (uint32_t)(vh*9 + vc + u)*16,
                     (const void*)&gv4[src + u]);
            if (it + 1 < NT) {
                const uint32_t nk = (it & 1) ? KS0 : KS1;
                CP16(sbase + 2u*nk + (uint32_t)(kr*17 + kc    )*16,
                     (const void*)&gk4[(tbase + j0 + 64 + kr) * 16 + kc]);
                CP16(sbase + 2u*nk + (uint32_t)(kr*17 + kc + 1)*16,
                     (const void*)&gk4[(tbase + j0 + 64 + kr) * 16 + kc + 1]);
            }
            CP_COMMIT();
        }

        // ---- PV(it-1): rows pr..+31, h ph..+63, from as_p/vs_p ----
        if (it > 0) {
            #pragma unroll
            for (int kt = 0; kt < 4; ++kt) {
                const int tok0 = kt * 16;
                uint32_t A0[4], A1[4], Bv[16];
                LDSM4(A0[0], A0[1], A0[2], A0[3],
                      sbase + 2u*(as_p + (pr + l15)*72 + tok0 + lh));
                LDSM4(A1[0], A1[1], A1[2], A1[3],
                      sbase + 2u*(as_p + (pr + 16 + l15)*72 + tok0 + lh));
                #pragma unroll
                for (int hp = 0; hp < 4; ++hp)
                    LDSM4(Bv[4*hp], Bv[4*hp+1], Bv[4*hp+2], Bv[4*hp+3],
                          sbase + 2u*(vs_p + (ph + hp*16 + brow2)*72 + tok0 + bcol2));
                #pragma unroll
                for (int j = 0; j < 8; ++j)
                    MMAF16(o[0][j], A0[0], A0[1], A0[2], A0[3], Bv[2*j], Bv[2*j+1]);
                #pragma unroll
                for (int j = 0; j < 8; ++j)
                    MMAF16(o[1][j], A1[0], A1[1], A1[2], A1[3], Bv[2*j], Bv[2*j+1]);
            }
        }

        // ---- sim(it): rows rm..+15, cols cn..+31, fp16 single-pass ----
        float s[4][4];
        #pragma unroll
        for (int i = 0; i < 4; ++i)
            #pragma unroll
            for (int j = 0; j < 4; ++j) s[i][j] = 0.0f;

        #pragma unroll
        for (int kk = 0; kk < 8; ++kk) {
            const int k0 = kk * 16;
            uint32_t a0, a1, a2, a3, bbv[8];
            LDSM4(a0, a1, a2, a3, sbase + 2u*(QS + (rm + l15)*136 + k0 + lh));
            LDSM4(bbv[0], bbv[1], bbv[2], bbv[3],
                  sbase + 2u*(ks + (cn + brow2)*136 + k0 + bcol2));
            LDSM4(bbv[4], bbv[5], bbv[6], bbv[7],
                  sbase + 2u*(ks + (cn + 16 + brow2)*136 + k0 + bcol2));
            #pragma unroll
            for (int nt = 0; nt < 4; ++nt)
                MMAF16(s[nt], a0, a1, a2, a3, bbv[2*nt], bbv[2*nt+1]);
        }

        // ---- relu^2/S^2 -> att (fp32 global) + as_c (fp16 * 2^30) ----
        {
            const int ra = rm + (l >> 2);
            const int rb = ra + 8;
            #pragma unroll
            for (int nt = 0; nt < 4; ++nt) {
                const int colg = cn + nt * 8 + 2 * (l & 3);
                float x;
                x = fmaxf(s[nt][0], 0.0f) * invS; const float a0 = x * x;
                x = fmaxf(s[nt][1], 0.0f) * invS; const float a1 = x * x;
                x = fmaxf(s[nt][2], 0.0f) * invS; const float a2 = x * x;
                x = fmaxf(s[nt][3], 0.0f) * invS; const float a3 = x * x;

                attb2[((size_t)(i0 + ra) * SS + j0 + colg) >> 1] = make_float2(a0, a1);
                attb2[((size_t)(i0 + rb) * SS + j0 + colg) >> 1] = make_float2(a2, a3);

                const unsigned short f0 = __half_as_ushort(__float2half_rn(a0 * ASCALE));
                const unsigned short f1 = __half_as_ushort(__float2half_rn(a1 * ASCALE));
                const unsigned short f2 = __half_as_ushort(__float2half_rn(a2 * ASCALE));
                const unsigned short f3 = __half_as_ushort(__float2half_rn(a3 * ASCALE));
                *(uint32_t*)(sb + as_c + ra * 72 + colg) = (uint32_t)f0 | ((uint32_t)f1 << 16);
                *(uint32_t*)(sb + as_c + rb * 72 + colg) = (uint32_t)f2 | ((uint32_t)f3 << 16);
            }
        }
    }

    // ---- drain: PV(NT-1) ----
    CP_WAIT(0);          // v(NT-1)
    __syncthreads();     // publish as(NT-1)
    {
        const uint32_t as_p = ((NT - 1) & 1) ? AS1 : AS0;
        const uint32_t vs_p = ((NT - 1) & 1) ? VS1 : VS0;
        #pragma unroll
        for (int kt = 0; kt < 4; ++kt) {
            const int tok0 = kt * 16;
            uint32_t A0[4], A1[4], Bv[16];
            LDSM4(A0[0], A0[1], A0[2], A0[3],
                  sbase + 2u*(as_p + (pr + l15)*72 + tok0 + lh));
            LDSM4(A1[0], A1[1], A1[2], A1[3],
                  sbase + 2u*(as_p + (pr + 16 + l15)*72 + tok0 + lh));
            #pragma unroll
            for (int hp = 0; hp < 4; ++hp)
                LDSM4(Bv[4*hp], Bv[4*hp+1], Bv[4*hp+2], Bv[4*hp+3],
                      sbase + 2u*(vs_p + (ph + hp*16 + brow2)*72 + tok0 + bcol2));
            #pragma unroll
            for (int j = 0; j < 8; ++j)
                MMAF16(o[0][j], A0[0], A0[1], A0[2], A0[3], Bv[2*j], Bv[2*j+1]);
            #pragma unroll
            for (int j = 0; j < 8; ++j)
                MMAF16(o[1][j], A1[0], A1[1], A1[2], A1[3], Bv[2*j], Bv[2*j+1]);
        }
    }

    // ---- epilogue: og = o * gate * 2^-30 -> smem, then @ W_out + b ----
    __syncthreads();
    float* og = (float*)sb;
    {
        const int ra0 = pr + (l >> 2);
        #pragma unroll
        for (int rg = 0; rg < 2; ++rg) {
            const int ra = ra0 + rg * 16;
            const int rb = ra + 8;
            #pragma unroll
            for (int j = 0; j < 8; ++j) {
                const int hc = ph + (j >> 1) * 16 + (j & 1) * 8 + 2 * (l & 3);
                const float2 ga = *(const float2*)&g_gate[(tbase + i0 + ra) * 256 + hc];
                const float2 gb = *(const float2*)&g_gate[(tbase + i0 + rb) * 256 + hc];
                *(float2*)&og[ra * OGS + hc] =
                    make_float2(o[rg][j][0] * ga.x * INV_ASCALE,
                                o[rg][j][1] * ga.y * INV_ASCALE);
                *(float2*)&og[rb * OGS + hc] =
                    make_float2(o[rg][j][2] * gb.x * INV_ASCALE,
                                o[rg][j][3] * gb.y * INV_ASCALE);
            }
        }
    }
    __syncthreads();

    {
        const int c = t & 127, r0 = t >> 7;
        float acc2[32];
        #pragma unroll
        for (int i = 0; i < 32; ++i) acc2[i] = 0.0f;
        for (int h = 0; h < 256; ++h) {
            const float wv = Wout[h * 128 + c];
            #pragma unroll
            for (int i = 0; i < 32; ++i)
                acc2[i] += og[(r0 + 4 * i) * OGS + h] * wv;
        }
        const float bb = bout[c];
        #pragma unroll
        for (int i = 0; i < 32; ++i)
            out[(tbase + i0 + r0 + 4 * i) * 128 + c] = acc2[i] + bb;
    }
}

// ---------------------------------------------------------------------------
extern "C" void kernel_launch(void* const* d_in, const int* in_sizes, int n_in,
                              void* d_out, int out_size)
{
    const float* query = (const float*)d_in[0];
    const float* value = (const float*)d_in[2];
    const float* ln_g  = (const float*)d_in[3];
    const float* ln_b  = (const float*)d_in[4];
    const float* Wg    = (const float*)d_in[5];
    const float* bg    = (const float*)d_in[6];
    const float* Wqk   = (const float*)d_in[7];
    const float* bqk   = (const float*)d_in[8];
    const float* gam   = (const float*)d_in[9];
    const float* bet   = (const float*)d_in[10];
    const float* Wout  = (const float*)d_in[11];
    const float* bout  = (const float*)d_in[12];

    float* out = (float*)d_out;                       // [B,S,D] first
    float* att = out + (size_t)BB * SS * DD;          // then [B,S,S]

    cudaFuncSetAttribute(k_pre_mma, cudaFuncAttributeMaxDynamicSharedMemorySize,
                         PRE_SMEM);
    cudaFuncSetAttribute(k_attn, cudaFuncAttributeMaxDynamicSharedMemorySize,
                         SMEM_BYTES);

    k_wconv<<<(HH * DD) / 256, 256>>>(Wqk, Wg);
    k_pre_mma<<<NTOK / 128, 512, PRE_SMEM>>>(query, value, ln_g, ln_b,
                                             bg, bqk, gam, bet);

    dim3 g2(SS / 128, BB);
    k_attn<<<g2, 512, SMEM_BYTES>>>(Wout, bout, out, att);
}